// round 2
// baseline (speedup 1.0000x reference)
#include <cuda_runtime.h>
#include <math.h>

// ---------------- problem constants ----------------
#define NN 512
#define BB 32
#define SEQ 8
#define NTAB 7001

static __device__ __constant__ float SQLF = 0.22360679775f;   // sqrt(0.05)

// ---------------- device scratch (no runtime alloc allowed) ----------------
__device__ float g_T[BB * NN * NN];     // T = M * rho          (33.5 MB)
__device__ float g_rho[BB * NN * NN];   // carried rho          (33.5 MB)
__device__ float g_Wt[NN * NN];         // W transposed
__device__ float g_uA[BB * NN], g_sA[BB * NN];   // ping-pong state
__device__ float g_uB[BB * NN], g_sB[BB * NN];
__device__ float g_ulin[BB * NN], g_diag[BB * NN];
__device__ float g_chi[BB * NN], g_sout[BB * NN];
__device__ float g_ue[BB * NN], g_se[BB * NN];
__device__ float g_ueraw[BB * NN], g_se2[BB * NN];

// Dawson-style tables
__device__ double d_I[NTAB], d_g[NTAB], d_h[NTAB];
__device__ float GTt[NTAB], GIt[NTAB], HIt[NTAB];

// ---------------- table construction (fp64, matches numpy cumtrapz) ----------------
__device__ __forceinline__ double block_excl_scan(double local, double* part, int t) {
    part[t] = local;
    __syncthreads();
    for (int off = 1; off < 1024; off <<= 1) {
        double v = (t >= off) ? part[t - off] : 0.0;
        __syncthreads();
        part[t] += v;
        __syncthreads();
    }
    double incl = part[t];
    __syncthreads();
    return incl - local;
}

__global__ void build_tables_kernel() {
    const double DX = 14.0 / 7000.0;
    __shared__ double part[1024];
    int t = threadIdx.x;
    int start = t * 7;
    int end = start + 7;
    if (start > NTAB) start = NTAB;
    if (end > NTAB) end = NTAB;

    // ---- Phase 1: I = exp(-100)/20 + cumtrapz(exp(-x^2)) ----
    {
        double local = 0.0;
        for (int i = start; i < end; i++) {
            if (i > 0) {
                double x0 = -10.0 + (i - 1) * DX, x1 = -10.0 + i * DX;
                local += 0.5 * (exp(-x0 * x0) + exp(-x1 * x1)) * DX;
            }
        }
        double run = block_excl_scan(local, part, t);
        const double A0 = exp(-100.0) / 20.0;
        for (int i = start; i < end; i++) {
            if (i > 0) {
                double x0 = -10.0 + (i - 1) * DX, x1 = -10.0 + i * DX;
                run += 0.5 * (exp(-x0 * x0) + exp(-x1 * x1)) * DX;
            }
            d_I[i] = A0 + run;
        }
    }
    __syncthreads();
    // ---- Phase 2: g = exp(x^2) * I ----
    for (int i = start; i < end; i++) {
        double x = -10.0 + i * DX;
        double g = exp(x * x) * d_I[i];
        d_g[i] = g;
        GTt[i] = (float)g;
    }
    __syncthreads();
    // ---- Phase 3: G = cumtrapz(g) ----
    {
        double local = 0.0;
        for (int i = start; i < end; i++)
            if (i > 0) local += 0.5 * (d_g[i - 1] + d_g[i]) * DX;
        double run = block_excl_scan(local, part, t);
        for (int i = start; i < end; i++) {
            if (i > 0) run += 0.5 * (d_g[i - 1] + d_g[i]) * DX;
            GIt[i] = (float)run;
        }
    }
    __syncthreads();
    // ---- Phase 4: h = exp(x^2) * cumtrapz(phi * g^2) ----
    {
        double local = 0.0;
        for (int i = start; i < end; i++) {
            if (i > 0) {
                double xa = -10.0 + (i - 1) * DX, xb = -10.0 + i * DX;
                double fa = exp(-xa * xa) * d_g[i - 1] * d_g[i - 1];
                double fb = exp(-xb * xb) * d_g[i] * d_g[i];
                local += 0.5 * (fa + fb) * DX;
            }
        }
        double run = block_excl_scan(local, part, t);
        for (int i = start; i < end; i++) {
            if (i > 0) {
                double xa = -10.0 + (i - 1) * DX, xb = -10.0 + i * DX;
                double fa = exp(-xa * xa) * d_g[i - 1] * d_g[i - 1];
                double fb = exp(-xb * xb) * d_g[i] * d_g[i];
                run += 0.5 * (fa + fb) * DX;
            }
            double x = -10.0 + i * DX;
            d_h[i] = exp(x * x) * run;
        }
    }
    __syncthreads();
    // ---- Phase 5: H = cumtrapz(h) ----
    {
        double local = 0.0;
        for (int i = start; i < end; i++)
            if (i > 0) local += 0.5 * (d_h[i - 1] + d_h[i]) * DX;
        double run = block_excl_scan(local, part, t);
        for (int i = start; i < end; i++) {
            if (i > 0) run += 0.5 * (d_h[i - 1] + d_h[i]) * DX;
            HIt[i] = (float)run;
        }
    }
}

// ---------------- small helper kernels ----------------
__global__ void transpose_kernel(const float* __restrict__ W) {
    __shared__ float tile[32][33];
    int x = blockIdx.x * 32 + threadIdx.x;   // col (k)
    int y = blockIdx.y * 32 + threadIdx.y;   // row (i)
    for (int j = 0; j < 32; j += 8)
        tile[threadIdx.y + j][threadIdx.x] = W[(size_t)(y + j) * NN + x];
    __syncthreads();
    int xo = blockIdx.y * 32 + threadIdx.x;  // i
    int yo = blockIdx.x * 32 + threadIdx.y;  // k
    for (int j = 0; j < 32; j += 8)
        g_Wt[(size_t)(yo + j) * NN + xo] = tile[threadIdx.x][threadIdx.y + j];
}

__global__ void init_copy_kernel(const float* __restrict__ u_in, const float* __restrict__ s_in) {
    int i = blockIdx.x * blockDim.x + threadIdx.x;
    if (i < BB * NN) { g_uA[i] = u_in[i]; g_sA[i] = s_in[i]; }
}

// external pathway GEMV-ish: one warp per (b,i)
__global__ void ext_gemm_kernel(const float* __restrict__ We, const float* __restrict__ ue_in,
                                const float* __restrict__ se_in, const float* __restrict__ be) {
    int warp = threadIdx.x >> 5, lane = threadIdx.x & 31;
    int i = blockIdx.x * 8 + warp;
    int b = blockIdx.y;
    const float* wr = We + (size_t)i * NN;
    const float* ur = ue_in + (size_t)b * NN;
    const float* sr = se_in + (size_t)b * NN;
    float s1 = 0.f, s2 = 0.f;
    for (int k = lane; k < NN; k += 32) {
        float w = wr[k], sv = sr[k];
        s1 += w * ur[k];
        s2 += w * w * sv * sv;
    }
#pragma unroll
    for (int o = 16; o; o >>= 1) {
        s1 += __shfl_xor_sync(0xffffffffu, s1, o);
        s2 += __shfl_xor_sync(0xffffffffu, s2, o);
    }
    if (lane == 0) {
        g_ueraw[b * NN + i] = s1 + be[i];
        g_se2[b * NN + i] = s2;
    }
}

__global__ void ext_bn_kernel(const float* __restrict__ wme, const float* __restrict__ bme) {
    int i = threadIdx.x;
    float m = 0.f;
    for (int b = 0; b < BB; b++) m += g_ueraw[b * NN + i];
    m *= (1.0f / BB);
    float v = 0.f;
    for (int b = 0; b < BB; b++) { float d = g_ueraw[b * NN + i] - m; v += d * d; }
    v *= (1.0f / BB);
    float f = wme[i] / sqrtf(v + 1e-5f);
    float af = fabsf(f);
    float bmv = bme[i];
    for (int b = 0; b < BB; b++) {
        int idx = b * NN + i;
        g_se[idx] = sqrtf(g_se2[idx]) * af;
        g_ue[idx] = (g_ueraw[idx] - m) * f + bmv;
    }
}

// per-step: u_lin = W u + b  and  diag(C) = sum_j T[i,j]*W[i,j]*s[j]; one warp per (b,i)
__global__ void diag_ulin_kernel(const float* __restrict__ W, const float* __restrict__ bias,
                                 const float* __restrict__ u_cur, const float* __restrict__ s_cur) {
    int warp = threadIdx.x >> 5, lane = threadIdx.x & 31;
    int i = blockIdx.x * 8 + warp;
    int b = blockIdx.y;
    const float* wr = W + (size_t)i * NN;
    const float* tr = g_T + ((size_t)b * NN + i) * NN;
    const float* ur = u_cur + (size_t)b * NN;
    const float* sr = s_cur + (size_t)b * NN;
    float s1 = 0.f, s2 = 0.f;
    for (int k = lane; k < NN; k += 32) {
        float w = wr[k];
        s1 += w * ur[k];
        s2 += tr[k] * w * sr[k];
    }
#pragma unroll
    for (int o = 16; o; o >>= 1) {
        s1 += __shfl_xor_sync(0xffffffffu, s1, o);
        s2 += __shfl_xor_sync(0xffffffffu, s2, o);
    }
    if (lane == 0) {
        g_ulin[b * NN + i] = s1 + bias[i];
        g_diag[b * NN + i] = s2;
    }
}

__device__ __forceinline__ float interp_tab(float x, const float* __restrict__ tab) {
    float t = (x + 10.0f) * 500.0f;
    int i = (int)t;
    i = max(0, min(i, NTAB - 2));
    float fr = t - (float)i;
    float lo = __ldg(&tab[i]);
    float hi = __ldg(&tab[i + 1]);
    return lo + fr * (hi - lo);
}

// BN (over batch) + add external + LIF moment activation; one thread per neuron.
// Writes NEW state into u_nxt/s_nxt (never aliases current-step s, which GEMM2 still needs).
__global__ void bn_act_kernel(const float* __restrict__ wm, const float* __restrict__ bm,
                              float* __restrict__ u_nxt, float* __restrict__ s_nxt,
                              float* __restrict__ ou, float* __restrict__ os) {
    int i = threadIdx.x;
    float m = 0.f;
    for (int b = 0; b < BB; b++) m += g_ulin[b * NN + i];
    m *= (1.0f / BB);
    float v = 0.f;
    for (int b = 0; b < BB; b++) { float d = g_ulin[b * NN + i] - m; v += d * d; }
    v *= (1.0f / BB);
    float f = wm[i] / sqrtf(v + 1e-5f);
    float af = fabsf(f);
    float bmv = bm[i];
#pragma unroll 4
    for (int b = 0; b < BB; b++) {
        int idx = b * NN + i;
        float so = sqrtf(fmaxf(g_diag[idx], 0.f));
        float sbn = so * af;
        float se = g_se[idx];
        float st = sqrtf(sbn * sbn + se * se);
        float ut = (g_ulin[idx] - m) * f + bmv + g_ue[idx];
        float ss = fmaxf(st, 1e-6f);
        float inv = 1.0f / (ss * SQLF);
        float ub = fminf(fmaxf((1.0f - ut) * inv, -10.f), 4.f);
        float lb = fminf(fmaxf((-ut) * inv, -10.f), 4.f);
        float dG = interp_tab(ub, GIt) - interp_tab(lb, GIt);
        float ua = 1.0f / (5.0f + 40.0f * dG);
        float dH = fmaxf(interp_tab(ub, HIt) - interp_tab(lb, HIt), 0.f);
        float sa = sqrtf(3200.0f * dH * ua * ua * ua);
        float dg = interp_tab(ub, GTt) - interp_tab(lb, GTt);
        float chi = ua * ua * 40.0f * dg / (SQLF * fmaxf(sa, 1e-9f));
        u_nxt[idx] = ua;
        s_nxt[idx] = sa;
        g_chi[idx] = chi;
        g_sout[idx] = so;
        if (ou) { ou[idx] = ua; os[idx] = sa; }
    }
}

// ---------------- batched GEMMs: 128x128 tile, 8x8 per thread, BK=8 ----------------
#define BM 128
#define BNT 128
#define BK 8

// GEMM1: T_b = (W * diag(s_b)) @ rho_b.   rho source switches on first step.
__global__ void __launch_bounds__(256, 2)
gemm1_kernel(const float* __restrict__ W, const float* __restrict__ rho_in, int use_input,
             const float* __restrict__ s_cur) {
    int b = blockIdx.z;
    const float* Bsrc = (use_input ? rho_in : (const float*)g_rho) + (size_t)b * NN * NN;
    float* Cdst = g_T + (size_t)b * NN * NN;
    const float* sv = s_cur + (size_t)b * NN;

    __shared__ float As[BK][BM];
    __shared__ float Bs[BK][BNT];
    __shared__ float sSv[NN];

    int tid = threadIdx.x;
    for (int k = tid; k < NN; k += 256) sSv[k] = sv[k];

    int tx = tid & 15, ty = tid >> 4;
    int rowBase = blockIdx.y * BM;
    int colBase = blockIdx.x * BNT;

    float acc[8][8];
#pragma unroll
    for (int i = 0; i < 8; i++)
#pragma unroll
        for (int j = 0; j < 8; j++) acc[i][j] = 0.f;

    int idx = tid * 4;
    int ar = idx >> 3, ac = idx & 7;
    int br = idx >> 7, bc = idx & 127;
    __syncthreads();

    for (int k0 = 0; k0 < NN; k0 += BK) {
        float4 va = *reinterpret_cast<const float4*>(&W[(size_t)(rowBase + ar) * NN + k0 + ac]);
        As[ac + 0][ar] = va.x * sSv[k0 + ac + 0];
        As[ac + 1][ar] = va.y * sSv[k0 + ac + 1];
        As[ac + 2][ar] = va.z * sSv[k0 + ac + 2];
        As[ac + 3][ar] = va.w * sSv[k0 + ac + 3];
        float4 vb = *reinterpret_cast<const float4*>(&Bsrc[(size_t)(k0 + br) * NN + colBase + bc]);
        *reinterpret_cast<float4*>(&Bs[br][bc]) = vb;
        __syncthreads();
#pragma unroll
        for (int kk = 0; kk < BK; kk++) {
            float a[8], bb[8];
            float4 a0 = *reinterpret_cast<float4*>(&As[kk][ty * 8]);
            float4 a1 = *reinterpret_cast<float4*>(&As[kk][ty * 8 + 4]);
            float4 b0 = *reinterpret_cast<float4*>(&Bs[kk][tx * 8]);
            float4 b1 = *reinterpret_cast<float4*>(&Bs[kk][tx * 8 + 4]);
            a[0]=a0.x; a[1]=a0.y; a[2]=a0.z; a[3]=a0.w; a[4]=a1.x; a[5]=a1.y; a[6]=a1.z; a[7]=a1.w;
            bb[0]=b0.x; bb[1]=b0.y; bb[2]=b0.z; bb[3]=b0.w; bb[4]=b1.x; bb[5]=b1.y; bb[6]=b1.z; bb[7]=b1.w;
#pragma unroll
            for (int mi = 0; mi < 8; mi++)
#pragma unroll
                for (int ni = 0; ni < 8; ni++) acc[mi][ni] += a[mi] * bb[ni];
        }
        __syncthreads();
    }
#pragma unroll
    for (int mi = 0; mi < 8; mi++) {
        float* crow = &Cdst[(size_t)(rowBase + ty * 8 + mi) * NN + colBase + tx * 8];
        *reinterpret_cast<float4*>(crow)     = make_float4(acc[mi][0], acc[mi][1], acc[mi][2], acc[mi][3]);
        *reinterpret_cast<float4*>(crow + 4) = make_float4(acc[mi][4], acc[mi][5], acc[mi][6], acc[mi][7]);
    }
}

// GEMM2: C_b = T_b @ (W*diag(s_b))^T, fused epilogue -> rho_out (unit diag, chi scaling)
__global__ void __launch_bounds__(256, 2)
gemm2_kernel(float* __restrict__ dst, const float* __restrict__ s_cur) {
    int b = blockIdx.z;
    const float* Asrc = g_T + (size_t)b * NN * NN;
    const float* sv = s_cur + (size_t)b * NN;
    float* Out = (dst ? dst : (float*)g_rho) + (size_t)b * NN * NN;

    __shared__ float As[BK][BM];
    __shared__ float Bs[BK][BNT];
    __shared__ float sSv[NN];

    int tid = threadIdx.x;
    for (int k = tid; k < NN; k += 256) sSv[k] = sv[k];

    int tx = tid & 15, ty = tid >> 4;
    int rowBase = blockIdx.y * BM;
    int colBase = blockIdx.x * BNT;

    float acc[8][8];
#pragma unroll
    for (int i = 0; i < 8; i++)
#pragma unroll
        for (int j = 0; j < 8; j++) acc[i][j] = 0.f;

    int idx = tid * 4;
    int ar = idx >> 3, ac = idx & 7;
    int br = idx >> 7, bc = idx & 127;
    __syncthreads();

    for (int k0 = 0; k0 < NN; k0 += BK) {
        float4 va = *reinterpret_cast<const float4*>(&Asrc[(size_t)(rowBase + ar) * NN + k0 + ac]);
        As[ac + 0][ar] = va.x;
        As[ac + 1][ar] = va.y;
        As[ac + 2][ar] = va.z;
        As[ac + 3][ar] = va.w;
        float sc = sSv[k0 + br];
        float4 vb = *reinterpret_cast<const float4*>(&g_Wt[(size_t)(k0 + br) * NN + colBase + bc]);
        vb.x *= sc; vb.y *= sc; vb.z *= sc; vb.w *= sc;
        *reinterpret_cast<float4*>(&Bs[br][bc]) = vb;
        __syncthreads();
#pragma unroll
        for (int kk = 0; kk < BK; kk++) {
            float a[8], bb[8];
            float4 a0 = *reinterpret_cast<float4*>(&As[kk][ty * 8]);
            float4 a1 = *reinterpret_cast<float4*>(&As[kk][ty * 8 + 4]);
            float4 b0 = *reinterpret_cast<float4*>(&Bs[kk][tx * 8]);
            float4 b1 = *reinterpret_cast<float4*>(&Bs[kk][tx * 8 + 4]);
            a[0]=a0.x; a[1]=a0.y; a[2]=a0.z; a[3]=a0.w; a[4]=a1.x; a[5]=a1.y; a[6]=a1.z; a[7]=a1.w;
            bb[0]=b0.x; bb[1]=b0.y; bb[2]=b0.z; bb[3]=b0.w; bb[4]=b1.x; bb[5]=b1.y; bb[6]=b1.z; bb[7]=b1.w;
#pragma unroll
            for (int mi = 0; mi < 8; mi++)
#pragma unroll
                for (int ni = 0; ni < 8; ni++) acc[mi][ni] += a[mi] * bb[ni];
        }
        __syncthreads();
    }

    // fused epilogue: C -> rho
    int gi0 = rowBase + ty * 8;
    int gl0 = colBase + tx * 8;
    const float* chb = g_chi + (size_t)b * NN;
    const float* sob = g_sout + (size_t)b * NN;
    float chI[8], soI[8], chL[8], soL[8];
#pragma unroll
    for (int m = 0; m < 8; m++) { chI[m] = chb[gi0 + m]; soI[m] = sob[gi0 + m]; }
#pragma unroll
    for (int n = 0; n < 8; n++) { chL[n] = chb[gl0 + n]; soL[n] = sob[gl0 + n]; }
#pragma unroll
    for (int mi = 0; mi < 8; mi++) {
        float r[8];
#pragma unroll
        for (int ni = 0; ni < 8; ni++) {
            float denom = soI[mi] * soL[ni];
            float q = (denom > 1e-12f) ? acc[mi][ni] / denom : 0.0f;
            r[ni] = ((gi0 + mi) == (gl0 + ni)) ? 1.0f : chI[mi] * chL[ni] * q;
        }
        float* orow = &Out[(size_t)(gi0 + mi) * NN + gl0];
        *reinterpret_cast<float4*>(orow)     = make_float4(r[0], r[1], r[2], r[3]);
        *reinterpret_cast<float4*>(orow + 4) = make_float4(r[4], r[5], r[6], r[7]);
    }
}

// ---------------- launch ----------------
extern "C" void kernel_launch(void* const* d_in, const int* in_sizes, int n_in,
                              void* d_out, int out_size) {
    const float* u_in     = (const float*)d_in[0];
    const float* s_in     = (const float*)d_in[1];
    const float* rho_in   = (const float*)d_in[2];
    const float* uext     = (const float*)d_in[3];
    const float* sext     = (const float*)d_in[4];
    const float* W        = (const float*)d_in[5];
    const float* bias     = (const float*)d_in[6];
    const float* Wext     = (const float*)d_in[7];
    const float* bext     = (const float*)d_in[8];
    const float* wmean    = (const float*)d_in[9];
    const float* bmean    = (const float*)d_in[10];
    const float* wmeanext = (const float*)d_in[11];
    const float* bmeanext = (const float*)d_in[12];
    (void)in_sizes; (void)n_in; (void)out_size;

    float* out = (float*)d_out;
    float* out_u = out;
    float* out_s = out + BB * NN;
    float* out_rho = out + 2 * BB * NN;

    build_tables_kernel<<<1, 1024>>>();
    transpose_kernel<<<dim3(16, 16), dim3(32, 8)>>>(W);
    init_copy_kernel<<<32, 512>>>(u_in, s_in);
    ext_gemm_kernel<<<dim3(64, 32), 256>>>(Wext, uext, sext, bext);
    ext_bn_kernel<<<1, 512>>>(wmeanext, bmeanext);

    // ping-pong state pointers (resolve device-symbol addresses once per launch)
    float *uA, *sA, *uB, *sB;
    cudaGetSymbolAddress((void**)&uA, g_uA);
    cudaGetSymbolAddress((void**)&sA, g_sA);
    cudaGetSymbolAddress((void**)&uB, g_uB);
    cudaGetSymbolAddress((void**)&sB, g_sB);

    dim3 gg(NN / BNT, NN / BM, BB);
    float* u_cur = uA; float* s_cur = sA;
    float* u_nxt = uB; float* s_nxt = sB;
    for (int t = 0; t < SEQ; t++) {
        bool last = (t == SEQ - 1);
        gemm1_kernel<<<gg, 256>>>(W, rho_in, t == 0 ? 1 : 0, s_cur);
        diag_ulin_kernel<<<dim3(64, 32), 256>>>(W, bias, u_cur, s_cur);
        bn_act_kernel<<<1, 512>>>(wmean, bmean, u_nxt, s_nxt,
                                  last ? out_u : (float*)nullptr,
                                  last ? out_s : (float*)nullptr);
        gemm2_kernel<<<gg, 256>>>(last ? out_rho : (float*)nullptr, s_cur);
        // swap
        float* tu = u_cur; u_cur = u_nxt; u_nxt = tu;
        float* ts = s_cur; s_cur = s_nxt; s_nxt = ts;
    }
}